// round 1
// baseline (speedup 1.0000x reference)
#include <cuda_runtime.h>

// Problem constants
#define Bb 2
#define Nn 100000
#define Ff 64
#define Ee 800000
#define EO 16
#define NO 64

// Scratch (device globals — no allocation allowed)
__device__ float g_P[Bb * Nn * 32];    // [b][n][0:16]=x·W1, [16:32]=x·W2
__device__ float g_agg[Bb * Nn * 16];  // aggregation buffer

// ---------------------------------------------------------------------------
// Branchless FFMA-only sigmoid: no MUFU (EX2/RCP rt=8/SMSP would bottleneck).
// exp(x) = 2^(x*log2e): round-to-nearest split, degree-5 Taylor on |f|<=0.5,
// exponent spliced via integer add to float bits. Reciprocal of (1+e) via
// magic-constant seed + 2 Newton iterations. Overall rel err ~1e-5.
// ---------------------------------------------------------------------------
__device__ __forceinline__ float fast_sigmoid(float x) {
    float t = x * 1.4426950408889634f;          // log2(e)
    t = fminf(fmaxf(t, -28.0f), 28.0f);         // saturate (sigmoid ~ 0/1 beyond)
    int   ei = __float2int_rn(t);
    float f  = t - (float)ei;                   // |f| <= 0.5
    float p  = 1.3333558e-3f;                   // ln2^5/120
    p = fmaf(p, f, 9.6181291e-3f);              // ln2^4/24
    p = fmaf(p, f, 5.5504109e-2f);              // ln2^3/6
    p = fmaf(p, f, 2.4022651e-1f);              // ln2^2/2
    p = fmaf(p, f, 6.9314718e-1f);              // ln2
    p = fmaf(p, f, 1.0f);
    float e = __int_as_float(__float_as_int(p) + (ei << 23));   // 2^t = exp(x)
    float d = 1.0f + e;
    float r = __int_as_float(0x7EF311C3 - __float_as_int(d));   // ~1/d seed
    r = r * fmaf(-d, r, 2.0f);                  // Newton 1
    r = r * fmaf(-d, r, 2.0f);                  // Newton 2
    return e * r;                               // e/(1+e) = sigmoid(x)
}

// ---------------------------------------------------------------------------
// K1: zero g_agg, then P[b,n,j] = sum_k x[b,n,k] * W1/W2[k,j].
// One warp per node; lane j owns output column j. Per-lane 64 weights hoisted
// into registers across the grid-stride loop; x row distributed via shuffles.
// ---------------------------------------------------------------------------
__global__ __launch_bounds__(256) void k1_precompute(
    const float* __restrict__ x, const float* __restrict__ W_e) {
    const int tid = blockIdx.x * blockDim.x + threadIdx.x;
    const int nth = gridDim.x * blockDim.x;

    // Zero the aggregation buffer (vectorized)
    const float4 z4 = make_float4(0.f, 0.f, 0.f, 0.f);
    for (int i = tid; i < (Bb * Nn * 16) / 4; i += nth)
        ((float4*)g_agg)[i] = z4;

    const int lane  = threadIdx.x & 31;
    const int col   = lane & 15;
    const int rbase = (lane >= 16) ? 64 : 0;    // lanes 16..31 -> W2 rows

    float w[64];
#pragma unroll
    for (int k = 0; k < 64; k++)
        w[k] = __ldg(W_e + (rbase + k) * EO + col);

    const int warpId = tid >> 5;
    const int nwarps = nth >> 5;
    for (int node = warpId; node < Bb * Nn; node += nwarps) {
        float2 xv = ((const float2*)(x + node * Ff))[lane];  // x[2*lane],x[2*lane+1]
        float acc = 0.f;
#pragma unroll
        for (int k = 0; k < 32; k++) {
            float a = __shfl_sync(0xffffffffu, xv.x, k);
            float b = __shfl_sync(0xffffffffu, xv.y, k);
            acc = fmaf(a, w[2 * k], acc);
            acc = fmaf(b, w[2 * k + 1], acc);
        }
        g_P[node * 32 + lane] = acc;
    }
}

// ---------------------------------------------------------------------------
// K2: per edge-instance (b,e): h = sigmoid(P1[src] + P2[tgt] + ew*w3 + b_e),
// then agg[tgt] += h, agg[src] -= h via red.global.add.v4.f32 (no-return,
// 16B per lane-op; 4x fewer LTS atomic transactions than scalar atomicAdd).
// 4 threads per edge-instance, thread q owns output quad q.
// ---------------------------------------------------------------------------
__global__ __launch_bounds__(256) void k2_edges(
    const int* __restrict__ esrc, const int* __restrict__ etgt,
    const float* __restrict__ ew, const float* __restrict__ W_e,
    const float* __restrict__ b_e) {
    const int tid0 = blockIdx.x * blockDim.x + threadIdx.x;
    const int nth  = gridDim.x * blockDim.x;   // multiple of 4 -> q invariant
    const int q    = tid0 & 3;

    const float4 w3 = ((const float4*)(W_e + 128 * EO))[q];  // ew row
    const float4 bq = ((const float4*)b_e)[q];

    for (int gid = tid0; gid < Bb * Ee * 4; gid += nth) {
        const int inst = gid >> 2;
        const int b    = (inst >= Ee) ? 1 : 0;
        const int e    = inst - b * Ee;

        const int   s  = __ldg(esrc + e);
        const int   t  = __ldg(etgt + e);
        const float wv = __ldg(ew + e);

        const float4 p1 = *(const float4*)(g_P + (b * Nn + s) * 32 + q * 4);
        const float4 p2 = *(const float4*)(g_P + (b * Nn + t) * 32 + 16 + q * 4);

        float4 h;
        h.x = fast_sigmoid(fmaf(wv, w3.x, p1.x + p2.x + bq.x));
        h.y = fast_sigmoid(fmaf(wv, w3.y, p1.y + p2.y + bq.y));
        h.z = fast_sigmoid(fmaf(wv, w3.z, p1.z + p2.z + bq.z));
        h.w = fast_sigmoid(fmaf(wv, w3.w, p1.w + p2.w + bq.w));

        float* ta = g_agg + (b * Nn + t) * 16 + q * 4;
        float* sa = g_agg + (b * Nn + s) * 16 + q * 4;
        asm volatile("red.global.add.v4.f32 [%0], {%1,%2,%3,%4};"
                     :: "l"(ta), "f"(h.x), "f"(h.y), "f"(h.z), "f"(h.w) : "memory");
        asm volatile("red.global.add.v4.f32 [%0], {%1,%2,%3,%4};"
                     :: "l"(sa), "f"(-h.x), "f"(-h.y), "f"(-h.z), "f"(-h.w) : "memory");
    }
}

// ---------------------------------------------------------------------------
// K3: out[b,n,:] = sigmoid(agg[b,n,:16] @ W_n[16,64] + b_n). One warp per
// node; lane owns output cols {lane, lane+32}; weights hoisted to registers.
// agg row read as 4 broadcast float4 loads (all lanes same address).
// ---------------------------------------------------------------------------
__global__ __launch_bounds__(256) void k3_nodes(
    const float* __restrict__ W_n, const float* __restrict__ b_n,
    float* __restrict__ out) {
    const int lane = threadIdx.x & 31;

    float wA[16], wB[16];
#pragma unroll
    for (int k = 0; k < 16; k++) {
        wA[k] = __ldg(W_n + k * NO + lane);
        wB[k] = __ldg(W_n + k * NO + lane + 32);
    }
    const float bA = __ldg(b_n + lane);
    const float bB = __ldg(b_n + lane + 32);

    const int tid    = blockIdx.x * blockDim.x + threadIdx.x;
    const int warpId = tid >> 5;
    const int nwarps = (gridDim.x * blockDim.x) >> 5;

    for (int node = warpId; node < Bb * Nn; node += nwarps) {
        const float4* ag = (const float4*)(g_agg + node * 16);
        float4 a0 = ag[0], a1 = ag[1], a2 = ag[2], a3 = ag[3];
        const float av[16] = {a0.x, a0.y, a0.z, a0.w, a1.x, a1.y, a1.z, a1.w,
                              a2.x, a2.y, a2.z, a2.w, a3.x, a3.y, a3.z, a3.w};
        float accA = bA, accB = bB;
#pragma unroll
        for (int k = 0; k < 16; k++) {
            accA = fmaf(av[k], wA[k], accA);
            accB = fmaf(av[k], wB[k], accB);
        }
        out[node * NO + lane]      = fast_sigmoid(accA);
        out[node * NO + lane + 32] = fast_sigmoid(accB);
    }
}

// ---------------------------------------------------------------------------
extern "C" void kernel_launch(void* const* d_in, const int* in_sizes, int n_in,
                              void* d_out, int out_size) {
    const float* x    = (const float*)d_in[0];
    const int*   esrc = (const int*)d_in[1];
    const int*   etgt = (const int*)d_in[2];
    const float* ew   = (const float*)d_in[3];
    const float* W_e  = (const float*)d_in[4];
    const float* b_e  = (const float*)d_in[5];
    const float* W_n  = (const float*)d_in[6];
    const float* b_n  = (const float*)d_in[7];
    float* out = (float*)d_out;

    const int blocks = 148 * 8;  // full resident wave of 256-thread CTAs
    k1_precompute<<<blocks, 256>>>(x, W_e);
    k2_edges<<<blocks, 256>>>(esrc, etgt, ew, W_e, b_e);
    k3_nodes<<<blocks, 256>>>(W_n, b_n, out);
}

// round 2
// speedup vs baseline: 1.1945x; 1.1945x over previous
#include <cuda_runtime.h>
#include <cstdint>

// Problem constants
#define Bb 2
#define Nn 100000
#define Ff 64
#define Ee 800000
#define EO 16
#define NO 64

// Scratch (device globals — no allocation allowed)
__device__ float g_P[Bb * Nn * 32];    // [b][n][0:16]=x·W1, [16:32]=x·W2
__device__ float g_agg[Bb * Nn * 16];  // aggregation buffer

// ---------------------------------------------------------------------------
// Packed fp32x2 helpers (Blackwell sm_100+; ptxas never emits these from C++)
// ---------------------------------------------------------------------------
__device__ __forceinline__ unsigned long long pack2(float a, float b) {
    unsigned long long r;
    asm("mov.b64 %0, {%1, %2};" : "=l"(r) : "f"(a), "f"(b));
    return r;
}
__device__ __forceinline__ float2 unpack2(unsigned long long v) {
    float2 r;
    asm("mov.b64 {%0, %1}, %2;" : "=f"(r.x), "=f"(r.y) : "l"(v));
    return r;
}
__device__ __forceinline__ unsigned long long fma2(unsigned long long a,
                                                   unsigned long long b,
                                                   unsigned long long c) {
    unsigned long long d;
    asm("fma.rn.f32x2 %0, %1, %2, %3;" : "=l"(d) : "l"(a), "l"(b), "l"(c));
    return d;
}

// ---------------------------------------------------------------------------
// MUFU sigmoid: 2 MUFU + 2 FMA-pipe ops. MUFU pipe is otherwise idle here
// (chip tput 74 warp-MUFU/cyc -> all 38.4M sigmoids ~18us, fully overlapped).
// x->-inf: ex2->inf, rcp(inf)=0 (ftz). x->+inf: ex2->0, rcp(1)=1. No clamps.
// ---------------------------------------------------------------------------
__device__ __forceinline__ float sigmoid_mufu(float x) {
    float e, r;
    asm("ex2.approx.ftz.f32 %0, %1;" : "=f"(e) : "f"(x * -1.4426950408889634f));
    asm("rcp.approx.ftz.f32 %0, %1;" : "=f"(r) : "f"(1.0f + e));
    return r;
}

// ---------------------------------------------------------------------------
// K1: zero g_agg, then P[b,n,j] = sum_k x[b,n,k] * W1/W2[k,j].
// Warp per node. x row staged in smem, read back as broadcast ld.shared.v2.b64
// (no shuffles, no pack movs); weight pairs pre-packed in registers; MACs via
// fma.rn.f32x2 with even/odd-k partial sums in two packed accumulators.
// Per node-lane: 16 LDS.128 + 32 fma2 for 64 MACs (was 64 FFMA + 64 SHFL).
// ---------------------------------------------------------------------------
__global__ __launch_bounds__(256) void k1_precompute(
    const float* __restrict__ x, const float* __restrict__ W_e) {
    __shared__ float xs[8][64];

    const int tid = blockIdx.x * blockDim.x + threadIdx.x;
    const int nth = gridDim.x * blockDim.x;

    // Zero the aggregation buffer (vectorized)
    const float4 z4 = make_float4(0.f, 0.f, 0.f, 0.f);
    for (int i = tid; i < (Bb * Nn * 16) / 4; i += nth)
        ((float4*)g_agg)[i] = z4;

    const int lane  = threadIdx.x & 31;
    const int winb  = threadIdx.x >> 5;
    const int col   = lane & 15;
    const int rbase = (lane >= 16) ? 64 : 0;    // lanes 16..31 -> W2 rows

    // Pre-packed weight pairs: w2[k] = {W[2k][col], W[2k+1][col]}
    unsigned long long w2[32];
#pragma unroll
    for (int k = 0; k < 32; k++)
        w2[k] = pack2(__ldg(W_e + (rbase + 2 * k) * EO + col),
                      __ldg(W_e + (rbase + 2 * k + 1) * EO + col));

    const uint32_t sbase = (uint32_t)__cvta_generic_to_shared(&xs[winb][0]);

    const int warpId = tid >> 5;
    const int nwarps = nth >> 5;
    for (int node = warpId; node < Bb * Nn; node += nwarps) {
        float2 xv = ((const float2*)(x + node * Ff))[lane];  // coalesced 256B
        ((float2*)xs[winb])[lane] = xv;
        __syncwarp();

        unsigned long long accA = 0ull, accB = 0ull;  // {0.f,0.f}
#pragma unroll
        for (int kk = 0; kk < 16; kk++) {
            unsigned long long a0, a1;
            asm volatile("ld.shared.v2.b64 {%0, %1}, [%2];"
                         : "=l"(a0), "=l"(a1) : "r"(sbase + kk * 16));
            accA = fma2(a0, w2[2 * kk], accA);
            accB = fma2(a1, w2[2 * kk + 1], accB);
        }
        __syncwarp();

        float2 sA = unpack2(accA), sB = unpack2(accB);
        g_P[node * 32 + lane] = (sA.x + sA.y) + (sB.x + sB.y);
    }
}

// ---------------------------------------------------------------------------
// K2: per edge-instance (b,e): h = sigmoid(P1[src] + P2[tgt] + ew*w3 + b_e),
// then agg[tgt] += h, agg[src] -= h via red.global.add.v4.f32.
// 4 threads per edge-instance, thread q owns output quad q. Sigmoids on MUFU.
// ---------------------------------------------------------------------------
__global__ __launch_bounds__(256) void k2_edges(
    const int* __restrict__ esrc, const int* __restrict__ etgt,
    const float* __restrict__ ew, const float* __restrict__ W_e,
    const float* __restrict__ b_e) {
    const int tid0 = blockIdx.x * blockDim.x + threadIdx.x;
    const int nth  = gridDim.x * blockDim.x;   // multiple of 4 -> q invariant
    const int q    = tid0 & 3;

    const float4 w3 = ((const float4*)(W_e + 128 * EO))[q];  // ew row
    const float4 bq = ((const float4*)b_e)[q];

    for (int gid = tid0; gid < Bb * Ee * 4; gid += nth) {
        const int inst = gid >> 2;
        const int b    = (inst >= Ee) ? 1 : 0;
        const int e    = inst - b * Ee;

        const int   s  = __ldg(esrc + e);
        const int   t  = __ldg(etgt + e);
        const float wv = __ldg(ew + e);

        const float4 p1 = *(const float4*)(g_P + (b * Nn + s) * 32 + q * 4);
        const float4 p2 = *(const float4*)(g_P + (b * Nn + t) * 32 + 16 + q * 4);

        float4 h;
        h.x = sigmoid_mufu(fmaf(wv, w3.x, p1.x + p2.x + bq.x));
        h.y = sigmoid_mufu(fmaf(wv, w3.y, p1.y + p2.y + bq.y));
        h.z = sigmoid_mufu(fmaf(wv, w3.z, p1.z + p2.z + bq.z));
        h.w = sigmoid_mufu(fmaf(wv, w3.w, p1.w + p2.w + bq.w));

        float* ta = g_agg + (b * Nn + t) * 16 + q * 4;
        float* sa = g_agg + (b * Nn + s) * 16 + q * 4;
        asm volatile("red.global.add.v4.f32 [%0], {%1,%2,%3,%4};"
                     :: "l"(ta), "f"(h.x), "f"(h.y), "f"(h.z), "f"(h.w) : "memory");
        asm volatile("red.global.add.v4.f32 [%0], {%1,%2,%3,%4};"
                     :: "l"(sa), "f"(-h.x), "f"(-h.y), "f"(-h.z), "f"(-h.w) : "memory");
    }
}

// ---------------------------------------------------------------------------
// K3: out[b,n,:] = sigmoid(agg[b,n,:16] @ W_n[16,64] + b_n). Warp per node;
// lane owns cols {lane, lane+32}. agg row loaded as packed 64-bit pairs,
// MACs via fma.rn.f32x2 (even/odd-k partial sums), sigmoid on MUFU.
// ---------------------------------------------------------------------------
__global__ __launch_bounds__(256) void k3_nodes(
    const float* __restrict__ W_n, const float* __restrict__ b_n,
    float* __restrict__ out) {
    const int lane = threadIdx.x & 31;

    // wA2[j] = {W_n[2j][lane], W_n[2j+1][lane]}, wB2 for col lane+32
    unsigned long long wA2[8], wB2[8];
#pragma unroll
    for (int j = 0; j < 8; j++) {
        wA2[j] = pack2(__ldg(W_n + (2 * j) * NO + lane),
                       __ldg(W_n + (2 * j + 1) * NO + lane));
        wB2[j] = pack2(__ldg(W_n + (2 * j) * NO + lane + 32),
                       __ldg(W_n + (2 * j + 1) * NO + lane + 32));
    }
    const float bA = __ldg(b_n + lane);
    const float bB = __ldg(b_n + lane + 32);

    const int tid    = blockIdx.x * blockDim.x + threadIdx.x;
    const int warpId = tid >> 5;
    const int nwarps = (gridDim.x * blockDim.x) >> 5;

    for (int node = warpId; node < Bb * Nn; node += nwarps) {
        const float* ag = g_agg + node * 16;
        unsigned long long a[8];
#pragma unroll
        for (int j = 0; j < 4; j++)  // 4x 16B broadcast loads
            asm volatile("ld.global.nc.v2.b64 {%0, %1}, [%2];"
                         : "=l"(a[2 * j]), "=l"(a[2 * j + 1])
                         : "l"(ag + 4 * j));

        unsigned long long accA = 0ull, accB = 0ull;
#pragma unroll
        for (int j = 0; j < 8; j++) {
            accA = fma2(a[j], wA2[j], accA);
            accB = fma2(a[j], wB2[j], accB);
        }
        float2 sA = unpack2(accA), sB = unpack2(accB);
        out[node * NO + lane]      = sigmoid_mufu(bA + sA.x + sA.y);
        out[node * NO + lane + 32] = sigmoid_mufu(bB + sB.x + sB.y);
    }
}

// ---------------------------------------------------------------------------
extern "C" void kernel_launch(void* const* d_in, const int* in_sizes, int n_in,
                              void* d_out, int out_size) {
    const float* x    = (const float*)d_in[0];
    const int*   esrc = (const int*)d_in[1];
    const int*   etgt = (const int*)d_in[2];
    const float* ew   = (const float*)d_in[3];
    const float* W_e  = (const float*)d_in[4];
    const float* b_e  = (const float*)d_in[5];
    const float* W_n  = (const float*)d_in[6];
    const float* b_n  = (const float*)d_in[7];
    float* out = (float*)d_out;

    const int blocks = 148 * 8;
    k1_precompute<<<blocks, 256>>>(x, W_e);
    k2_edges<<<blocks, 256>>>(esrc, etgt, ew, W_e, b_e);
    k3_nodes<<<blocks, 256>>>(W_n, b_n, out);
}

// round 4
// speedup vs baseline: 1.3266x; 1.1106x over previous
#include <cuda_runtime.h>
#include <cstdint>

// Problem constants
#define Bb 2
#define Nn 100000
#define Ff 64
#define Ee 800000
#define EO 16
#define NO 64

// Scratch (device globals — no allocation allowed)
__device__ float g_P[Bb * Nn * 32];    // [b][n][0:16]=x·W1, [16:32]=x·W2
__device__ float g_agg[Bb * Nn * 16];  // aggregation buffer

// ---------------------------------------------------------------------------
// Packed fp32x2 helpers (Blackwell sm_100+; ptxas never emits these from C++)
// ---------------------------------------------------------------------------
__device__ __forceinline__ unsigned long long pack2(float a, float b) {
    unsigned long long r;
    asm("mov.b64 %0, {%1, %2};" : "=l"(r) : "f"(a), "f"(b));
    return r;
}
__device__ __forceinline__ float2 unpack2(unsigned long long v) {
    float2 r;
    asm("mov.b64 {%0, %1}, %2;" : "=f"(r.x), "=f"(r.y) : "l"(v));
    return r;
}
__device__ __forceinline__ unsigned long long fma2(unsigned long long a,
                                                   unsigned long long b,
                                                   unsigned long long c) {
    unsigned long long d;
    asm("fma.rn.f32x2 %0, %1, %2, %3;" : "=l"(d) : "l"(a), "l"(b), "l"(c));
    return d;
}

// ---------------------------------------------------------------------------
// MUFU sigmoid: 2 MUFU + 2 FMA-pipe ops; MUFU pipe otherwise idle.
// x->-inf: ex2->inf, rcp(inf)=0 (ftz). x->+inf: ex2->0, rcp(1)=1. No clamps.
// ---------------------------------------------------------------------------
__device__ __forceinline__ float sigmoid_mufu(float x) {
    float e, r;
    asm("ex2.approx.ftz.f32 %0, %1;" : "=f"(e) : "f"(x * -1.4426950408889634f));
    asm("rcp.approx.ftz.f32 %0, %1;" : "=f"(r) : "f"(1.0f + e));
    return r;
}

// ---------------------------------------------------------------------------
// K1: zero g_agg, then P[b,n,j] = sum_k x[b,n,k] * W1/W2[k,j].
// Warp processes TWO nodes per iteration: one LDG.128/lane covers both rows
// (512B coalesced), one STS.128, ONE __syncwarp per pair (was 4), and the
// inner loop runs 4 independent fma2 chains (2 per node) for 2x the ILP.
// Double-buffered smem slot removes the trailing WAR sync. 128-thread CTAs:
// at ~100 regs -> 5 CTAs = 20 warps/SM (vs 16 with 256-thread CTAs).
// ---------------------------------------------------------------------------
__global__ __launch_bounds__(128) void k1_precompute(
    const float* __restrict__ x, const float* __restrict__ W_e) {
    __shared__ float xs[4][2][128];   // [warp][buf][2 node rows]

    const int tid = blockIdx.x * blockDim.x + threadIdx.x;
    const int nth = gridDim.x * blockDim.x;

    // Zero the aggregation buffer (vectorized)
    const float4 z4 = make_float4(0.f, 0.f, 0.f, 0.f);
    for (int i = tid; i < (Bb * Nn * 16) / 4; i += nth)
        ((float4*)g_agg)[i] = z4;

    const int lane  = threadIdx.x & 31;
    const int winb  = threadIdx.x >> 5;
    const int col   = lane & 15;
    const int rbase = (lane >= 16) ? 64 : 0;    // lanes 16..31 -> W2 rows

    // Pre-packed weight pairs: w2[k] = {W[2k][col], W[2k+1][col]}
    unsigned long long w2[32];
#pragma unroll
    for (int k = 0; k < 32; k++)
        w2[k] = pack2(__ldg(W_e + (rbase + 2 * k) * EO + col),
                      __ldg(W_e + (rbase + 2 * k + 1) * EO + col));

    const uint32_t sb0 = (uint32_t)__cvta_generic_to_shared(&xs[winb][0][0]);
    const uint32_t sb1 = (uint32_t)__cvta_generic_to_shared(&xs[winb][1][0]);

    const int warpId = tid >> 5;
    const int nwarps = nth >> 5;
    int p = 0;
    for (int pair = warpId; pair < (Bb * Nn) / 2; pair += nwarps) {
        // Load two consecutive node rows (512B) with one LDG.128 per lane.
        const float4 xv = ((const float4*)(x + (size_t)pair * 128))[lane];
        const uint32_t sb = p ? sb1 : sb0;
        ((float4*)(p ? xs[winb][1] : xs[winb][0]))[lane] = xv;
        __syncwarp();

        unsigned long long accA0 = 0ull, accB0 = 0ull;
        unsigned long long accA1 = 0ull, accB1 = 0ull;
#pragma unroll
        for (int kk = 0; kk < 16; kk++) {
            unsigned long long a0, a1, b0, b1;
            asm volatile("ld.shared.v2.b64 {%0, %1}, [%2];"
                         : "=l"(a0), "=l"(a1) : "r"(sb + kk * 16));
            asm volatile("ld.shared.v2.b64 {%0, %1}, [%2];"
                         : "=l"(b0), "=l"(b1) : "r"(sb + 256 + kk * 16));
            accA0 = fma2(a0, w2[2 * kk],     accA0);
            accB0 = fma2(a1, w2[2 * kk + 1], accB0);
            accA1 = fma2(b0, w2[2 * kk],     accA1);
            accB1 = fma2(b1, w2[2 * kk + 1], accB1);
        }

        float2 sA0 = unpack2(accA0), sB0 = unpack2(accB0);
        float2 sA1 = unpack2(accA1), sB1 = unpack2(accB1);
        g_P[(size_t)pair * 64 + lane]      = (sA0.x + sA0.y) + (sB0.x + sB0.y);
        g_P[(size_t)pair * 64 + 32 + lane] = (sA1.x + sA1.y) + (sB1.x + sB1.y);
        p ^= 1;   // double buffer: no trailing sync needed
    }
}

// ---------------------------------------------------------------------------
// K2: per edge-instance (b,e): h = sigmoid(P1[src] + P2[tgt] + ew*w3 + b_e),
// then agg[tgt] += h, agg[src] -= h via red.global.add.v4.f32.
// 4 threads per edge-instance, thread q owns output quad q. Sigmoids on MUFU.
// Batch split hoisted out of the hot loop; P gathers on the nc path.
// ---------------------------------------------------------------------------
__global__ __launch_bounds__(256) void k2_edges(
    const int* __restrict__ esrc, const int* __restrict__ etgt,
    const float* __restrict__ ew, const float* __restrict__ W_e,
    const float* __restrict__ b_e) {
    const int tid0 = blockIdx.x * blockDim.x + threadIdx.x;
    const int nth  = gridDim.x * blockDim.x;   // multiple of 4 -> q invariant
    const int q    = tid0 & 3;

    const float4 w3 = ((const float4*)(W_e + 128 * EO))[q];  // ew row
    const float4 bq = ((const float4*)b_e)[q];

#pragma unroll 1
    for (int b = 0; b < Bb; b++) {
        const float* Pb = g_P + (size_t)b * Nn * 32;
        float* aggb     = g_agg + (size_t)b * Nn * 16;

        for (int gid = tid0; gid < Ee * 4; gid += nth) {
            const int e = gid >> 2;

            const int   s  = __ldg(esrc + e);
            const int   t  = __ldg(etgt + e);
            const float wv = __ldg(ew + e);

            const float4 p1 = __ldg((const float4*)(Pb + (size_t)s * 32 + q * 4));
            const float4 p2 = __ldg((const float4*)(Pb + (size_t)t * 32 + 16 + q * 4));

            float4 h;
            h.x = sigmoid_mufu(fmaf(wv, w3.x, p1.x + p2.x + bq.x));
            h.y = sigmoid_mufu(fmaf(wv, w3.y, p1.y + p2.y + bq.y));
            h.z = sigmoid_mufu(fmaf(wv, w3.z, p1.z + p2.z + bq.z));
            h.w = sigmoid_mufu(fmaf(wv, w3.w, p1.w + p2.w + bq.w));

            float* ta = aggb + (size_t)t * 16 + q * 4;
            float* sa = aggb + (size_t)s * 16 + q * 4;
            asm volatile("red.global.add.v4.f32 [%0], {%1,%2,%3,%4};"
                         :: "l"(ta), "f"(h.x), "f"(h.y), "f"(h.z), "f"(h.w) : "memory");
            asm volatile("red.global.add.v4.f32 [%0], {%1,%2,%3,%4};"
                         :: "l"(sa), "f"(-h.x), "f"(-h.y), "f"(-h.z), "f"(-h.w) : "memory");
        }
    }
}

// ---------------------------------------------------------------------------
// K3: out[b,n,:] = sigmoid(agg[b,n,:16] @ W_n[16,64] + b_n). Warp per node;
// lane owns cols {lane, lane+32}. agg row loaded as packed 64-bit pairs,
// MACs via fma.rn.f32x2 (even/odd-k partial sums), sigmoid on MUFU.
// ---------------------------------------------------------------------------
__global__ __launch_bounds__(256) void k3_nodes(
    const float* __restrict__ W_n, const float* __restrict__ b_n,
    float* __restrict__ out) {
    const int lane = threadIdx.x & 31;

    // wA2[j] = {W_n[2j][lane], W_n[2j+1][lane]}, wB2 for col lane+32
    unsigned long long wA2[8], wB2[8];
#pragma unroll
    for (int j = 0; j < 8; j++) {
        wA2[j] = pack2(__ldg(W_n + (2 * j) * NO + lane),
                       __ldg(W_n + (2 * j + 1) * NO + lane));
        wB2[j] = pack2(__ldg(W_n + (2 * j) * NO + lane + 32),
                       __ldg(W_n + (2 * j + 1) * NO + lane + 32));
    }
    const float bA = __ldg(b_n + lane);
    const float bB = __ldg(b_n + lane + 32);

    const int tid    = blockIdx.x * blockDim.x + threadIdx.x;
    const int warpId = tid >> 5;
    const int nwarps = (gridDim.x * blockDim.x) >> 5;

    for (int node = warpId; node < Bb * Nn; node += nwarps) {
        const float* ag = g_agg + (size_t)node * 16;
        unsigned long long a[8];
#pragma unroll
        for (int j = 0; j < 4; j++)  // 4x 16B broadcast loads
            asm volatile("ld.global.nc.v2.b64 {%0, %1}, [%2];"
                         : "=l"(a[2 * j]), "=l"(a[2 * j + 1])
                         : "l"(ag + 4 * j));

        unsigned long long accA = 0ull, accB = 0ull;
#pragma unroll
        for (int j = 0; j < 8; j++) {
            accA = fma2(a[j], wA2[j], accA);
            accB = fma2(a[j], wB2[j], accB);
        }
        float2 sA = unpack2(accA), sB = unpack2(accB);
        out[(size_t)node * NO + lane]      = sigmoid_mufu(bA + sA.x + sA.y);
        out[(size_t)node * NO + lane + 32] = sigmoid_mufu(bB + sB.x + sB.y);
    }
}

// ---------------------------------------------------------------------------
extern "C" void kernel_launch(void* const* d_in, const int* in_sizes, int n_in,
                              void* d_out, int out_size) {
    const float* x    = (const float*)d_in[0];
    const int*   esrc = (const int*)d_in[1];
    const int*   etgt = (const int*)d_in[2];
    const float* ew   = (const float*)d_in[3];
    const float* W_e  = (const float*)d_in[4];
    const float* b_e  = (const float*)d_in[5];
    const float* W_n  = (const float*)d_in[6];
    const float* b_n  = (const float*)d_in[7];
    float* out = (float*)d_out;

    k1_precompute<<<148 * 16, 128>>>(x, W_e);
    k2_edges<<<148 * 8, 256>>>(esrc, etgt, ew, W_e, b_e);
    k3_nodes<<<148 * 8, 256>>>(W_n, b_n, out);
}